// round 1
// baseline (speedup 1.0000x reference)
#include <cuda_runtime.h>
#include <cstdint>

// ---------------------------------------------------------------------------
// Problem: patches [16384][9] f32, db [16384][9] f32.
// mask[i] = all_j ( dot(p_i,d_j) / (||p_i|| ||d_j||) < 0.9 )
// out = [ db (147456 f32) ; mask[i] ? p_i : 0 (147456 f32) ]
// ---------------------------------------------------------------------------

#define N_PATCH 16384
#define N_DB    16384
#define ROW     9
#define HALF_OUT (N_DB * ROW)          // 147456
#define TOTAL_OUT (2 * HALF_OUT)       // 294912

// db rows stored pre-duplicated for f32x2 consumption:
// [v0,v0, v1,v1, ..., v8,v8, inv,inv]  -> 20 floats = 80 bytes = 5 x 16B
__device__ float g_dnd[N_DB * 20];
__device__ float g_thr[N_PATCH];       // 0.9 * ||p_i||
__device__ int   g_hit[N_PATCH];

// ------------------------- f32x2 helpers -----------------------------------
__device__ __forceinline__ unsigned long long pack2(float a, float b) {
    unsigned long long r;
    asm("mov.b64 %0, {%1, %2};" : "=l"(r) : "f"(a), "f"(b));
    return r;
}
__device__ __forceinline__ void unpack2(float& a, float& b, unsigned long long v) {
    asm("mov.b64 {%0, %1}, %2;" : "=f"(a), "=f"(b) : "l"(v));
}
__device__ __forceinline__ unsigned long long fma2(unsigned long long a,
                                                   unsigned long long b,
                                                   unsigned long long c) {
    unsigned long long r;
    asm("fma.rn.f32x2 %0, %1, %2, %3;" : "=l"(r) : "l"(a), "l"(b), "l"(c));
    return r;
}
__device__ __forceinline__ unsigned long long mul2(unsigned long long a,
                                                   unsigned long long b) {
    unsigned long long r;
    asm("mul.rn.f32x2 %0, %1, %2;" : "=l"(r) : "l"(a), "l"(b));
    return r;
}

// ------------------------- prep kernel -------------------------------------
// threads [0, 16384): db row j -> duplicated row + inv norm; zero hit flag
// threads [16384, 32768): patch i -> threshold 0.9*||p_i||
__global__ void prep_kernel(const float* __restrict__ patches,
                            const float* __restrict__ db) {
    int idx = blockIdx.x * blockDim.x + threadIdx.x;
    if (idx < N_DB) {
        int j = idx;
        float v[ROW];
        double s = 0.0;
#pragma unroll
        for (int k = 0; k < ROW; k++) {
            v[k] = db[j * ROW + k];
            s += (double)v[k] * (double)v[k];
        }
        float inv = (float)(1.0 / sqrt(s));
        float* o = g_dnd + j * 20;
#pragma unroll
        for (int k = 0; k < ROW; k++) {
            o[2 * k]     = v[k];
            o[2 * k + 1] = v[k];
        }
        o[18] = inv;
        o[19] = inv;
        g_hit[j] = 0;
    } else if (idx < N_DB + N_PATCH) {
        int i = idx - N_DB;
        double s = 0.0;
#pragma unroll
        for (int k = 0; k < ROW; k++) {
            float v = patches[i * ROW + k];
            s += (double)v * (double)v;
        }
        g_thr[i] = 0.9f * (float)sqrt(s);
    }
}

// ------------------------- similarity kernel -------------------------------
#define B_THREADS 128
#define IT        8                    // patches per thread (4 f32x2 pairs)
#define NPAIR     (IT / 2)
#define ITILE     (B_THREADS * IT)     // 1024 patches per block (i)
#define NBI       (N_PATCH / ITILE)    // 16
#define JCHUNK    512
#define NBJ       (N_DB / JCHUNK)      // 32

__global__ __launch_bounds__(B_THREADS)
void sim_kernel(const float* __restrict__ patches) {
    const int i0 = blockIdx.x * ITILE + threadIdx.x * IT;
    const int j0 = blockIdx.y * JCHUNK;

    // Pack this thread's 8 patches as 4 f32x2 pairs (36 u64 regs).
    unsigned long long pk[NPAIR][ROW];
    float thr[IT];
#pragma unroll
    for (int pr = 0; pr < NPAIR; pr++) {
        const int ia = i0 + 2 * pr;
        const int ib = ia + 1;
#pragma unroll
        for (int k = 0; k < ROW; k++) {
            pk[pr][k] = pack2(patches[ia * ROW + k], patches[ib * ROW + k]);
        }
        thr[2 * pr]     = g_thr[ia];
        thr[2 * pr + 1] = g_thr[ib];
    }

    float mx[IT];
#pragma unroll
    for (int p = 0; p < IT; p++) mx[p] = -3.0e38f;

    // db rows: 80 B each = 5 x ulonglong2, uniform address across the warp
    const ulonglong2* __restrict__ dq =
        (const ulonglong2*)(g_dnd + (size_t)j0 * 20);

#pragma unroll 2
    for (int j = 0; j < JCHUNK; j++) {
        const ulonglong2 q0 = dq[0];   // (v0,v0) (v1,v1)
        const ulonglong2 q1 = dq[1];   // (v2,v2) (v3,v3)
        const ulonglong2 q2 = dq[2];   // (v4,v4) (v5,v5)
        const ulonglong2 q3 = dq[3];   // (v6,v6) (v7,v7)
        const ulonglong2 q4 = dq[4];   // (v8,v8) (inv,inv)
        dq += 5;

#pragma unroll
        for (int pr = 0; pr < NPAIR; pr++) {
            unsigned long long acc = mul2(pk[pr][0], q0.x);
            acc = fma2(pk[pr][1], q0.y, acc);
            acc = fma2(pk[pr][2], q1.x, acc);
            acc = fma2(pk[pr][3], q1.y, acc);
            acc = fma2(pk[pr][4], q2.x, acc);
            acc = fma2(pk[pr][5], q2.y, acc);
            acc = fma2(pk[pr][6], q3.x, acc);
            acc = fma2(pk[pr][7], q3.y, acc);
            acc = fma2(pk[pr][8], q4.x, acc);
            acc = mul2(acc, q4.y);     // scale by 1/||d_j||
            float a, b;
            unpack2(a, b, acc);
            mx[2 * pr]     = fmaxf(mx[2 * pr], a);
            mx[2 * pr + 1] = fmaxf(mx[2 * pr + 1], b);
        }
    }

#pragma unroll
    for (int p = 0; p < IT; p++) {
        if (mx[p] >= thr[p]) g_hit[i0 + p] = 1;   // benign race: same value
    }
}

// ------------------------- output kernel -----------------------------------
__global__ void out_kernel(const float* __restrict__ patches,
                           const float* __restrict__ db,
                           float* __restrict__ out) {
    int idx = blockIdx.x * blockDim.x + threadIdx.x;
    if (idx < HALF_OUT) {
        out[idx] = db[idx];
    } else if (idx < TOTAL_OUT) {
        int t = idx - HALF_OUT;
        int i = t / ROW;
        out[idx] = g_hit[i] ? 0.0f : patches[t];
    }
}

// ------------------------- launch ------------------------------------------
extern "C" void kernel_launch(void* const* d_in, const int* in_sizes, int n_in,
                              void* d_out, int out_size) {
    const float* patches = (const float*)d_in[0];   // [2,8,1024,3,3] = [16384][9]
    const float* db      = (const float*)d_in[1];   // [16384][9]
    float* out           = (float*)d_out;           // [32768][9]

    prep_kernel<<<(N_DB + N_PATCH + 255) / 256, 256>>>(patches, db);
    sim_kernel<<<dim3(NBI, NBJ), B_THREADS>>>(patches);
    out_kernel<<<(TOTAL_OUT + 255) / 256, 256>>>(patches, db, out);
}